// round 2
// baseline (speedup 1.0000x reference)
#include <cuda_runtime.h>
#include <math.h>

#define B_ 4
#define C_ 64
#define H_ 128
#define W_ 128
#define O_ 64
#define HW_ (H_*W_)

// Scratch (static device globals -- allocation is forbidden)
__device__ float g_offs[(size_t)B_ * 18 * HW_];   // 18 offset channels per batch
__device__ float g_modmean[(size_t)B_ * HW_];     // mean of 9 sigmoids

// ---- packed f32x2 helpers (sm_103a) ---------------------------------------
__device__ __forceinline__ unsigned long long pk2(float lo, float hi) {
    unsigned long long r;
    asm("mov.b64 %0, {%1, %2};" : "=l"(r) : "f"(lo), "f"(hi));
    return r;
}
__device__ __forceinline__ void upk2(unsigned long long v, float& lo, float& hi) {
    asm("mov.b64 {%0, %1}, %2;" : "=f"(lo), "=f"(hi) : "l"(v));
}
__device__ __forceinline__ void fma2(unsigned long long& d,
                                     unsigned long long a,
                                     unsigned long long b) {
    asm("fma.rn.f32x2 %0, %1, %2, %3;" : "=l"(d) : "l"(a), "l"(b), "l"(d));
}

// ---------------------------------------------------------------------------
// Kernel 1: fused offset-conv (18 ch) + modulation-conv (9 ch) + sigmoid-mean.
// 16x16 output tile per block. x tile (64 x 18 x 18) and j-transposed weights
// (row padded to 28 for float4) staged in dynamic smem (~144KB).
// ---------------------------------------------------------------------------
__global__ __launch_bounds__(256) void k_offmod(
    const float* __restrict__ x,
    const float* __restrict__ ow, const float* __restrict__ ob,
    const float* __restrict__ mw, const float* __restrict__ mb)
{
    extern __shared__ float sm1[];
    float* xs = sm1;                 // [c][18][18] -> c*324 + y*18 + x
    float* wt = sm1 + 64 * 324;      // [(c*9+kk)][28] j-contiguous

    const int tid = threadIdx.x;
    const int tx = tid & 15, ty = tid >> 4;
    const int w0 = blockIdx.x * 16, h0 = blockIdx.y * 16;
    const int b = blockIdx.z;
    const float* xb = x + (size_t)b * C_ * HW_;

    // cooperative load: x tile with zero padding
    for (int i = tid; i < 64 * 324; i += 256) {
        int c = i / 324, r = i % 324;
        int yy = r / 18, xx = r % 18;
        int gy = h0 + yy - 1, gx = w0 + xx - 1;
        float v = 0.f;
        if (gy >= 0 && gy < H_ && gx >= 0 && gx < W_)
            v = xb[c * HW_ + gy * W_ + gx];
        xs[i] = v;
    }
    // cooperative load: transposed weights wt[(c*9+kk)*28 + j]
    // j in [0,18): offset weights; j in [18,27): modulation weights; j=27 pad
    for (int i = tid; i < 64 * 9 * 28; i += 256) {
        int j = i % 28;
        int ck = i / 28;              // c*9 + kk, in [0,576)
        float v = 0.f;
        if (j < 18)       v = ow[(size_t)j * 576 + ck];
        else if (j < 27)  v = mw[(size_t)(j - 18) * 576 + ck];
        wt[i] = v;
    }
    __syncthreads();

    float acc[28];
#pragma unroll
    for (int j = 0; j < 28; ++j) acc[j] = 0.f;

    for (int c = 0; c < 64; ++c) {
#pragma unroll
        for (int kk = 0; kk < 9; ++kk) {
            const int ky = kk / 3, kx = kk % 3;
            const float xv = xs[c * 324 + (ty + ky) * 18 + (tx + kx)];
            const float4* w4 = reinterpret_cast<const float4*>(wt + (c * 9 + kk) * 28);
#pragma unroll
            for (int q = 0; q < 7; ++q) {
                float4 wv = w4[q];
                acc[4 * q + 0] = fmaf(xv, wv.x, acc[4 * q + 0]);
                acc[4 * q + 1] = fmaf(xv, wv.y, acc[4 * q + 1]);
                acc[4 * q + 2] = fmaf(xv, wv.z, acc[4 * q + 2]);
                acc[4 * q + 3] = fmaf(xv, wv.w, acc[4 * q + 3]);
            }
        }
    }

    const int h = h0 + ty, w = w0 + tx;
    const int hw = h * W_ + w;
#pragma unroll
    for (int j = 0; j < 18; ++j)
        g_offs[((size_t)b * 18 + j) * HW_ + hw] = acc[j] + __ldg(&ob[j]);

    float s = 0.f;
#pragma unroll
    for (int j = 0; j < 9; ++j) {
        float z = acc[18 + j] + __ldg(&mb[j]);
        s += 1.f / (1.f + __expf(-z));
    }
    g_modmean[(size_t)b * HW_ + hw] = s * (1.f / 9.f);
}

// ---------------------------------------------------------------------------
// Kernel 2: deformable gather + 576x64 per-pixel GEMV + modulation epilogue.
// One thread per output pixel, 32 packed f32x2 accumulators (fma.rn.f32x2).
// k-outer loop stages the per-k weight slice transposed ([c][o], o-contig)
// in 16KB static smem, read back as ulonglong2 (LDS.128, zero repack).
// ---------------------------------------------------------------------------
__global__ __launch_bounds__(256) void k_main(
    const float* __restrict__ x,
    const float* __restrict__ weight,
    const float* __restrict__ bias,
    float* __restrict__ out)
{
    __shared__ float wk_s[64 * 64];   // [c][o]

    const int tid = threadIdx.x;
    const int tx = tid & 15, ty = tid >> 4;
    const int b = blockIdx.z;
    const int w = blockIdx.x * 16 + tx;
    const int h = blockIdx.y * 16 + ty;
    const int hw = h * W_ + w;
    const float* xb = x + (size_t)b * C_ * HW_;

    unsigned long long acc2[32];
#pragma unroll
    for (int q = 0; q < 32; ++q) acc2[q] = 0ull;

    for (int k = 0; k < 9; ++k) {
        __syncthreads();
        // stage weight[:, :, k] transposed -> wk_s[c*64 + o]
        for (int i = tid; i < 4096; i += 256) {
            int o = i >> 6, c = i & 63;
            wk_s[c * 64 + o] = weight[((size_t)o * 64 + c) * 9 + k];
        }
        __syncthreads();

        const int ky = k / 3 - 1, kx = k % 3 - 1;
        const float sy = (float)(h + ky) + g_offs[((size_t)b * 18 + k) * HW_ + hw];
        const float sx = (float)(w + kx) + g_offs[((size_t)b * 18 + 9 + k) * HW_ + hw];

        const float y0f = floorf(sy), x0f = floorf(sx);
        const float wy1 = sy - y0f, wx1 = sx - x0f;
        const float wy0 = 1.f - wy1, wx0 = 1.f - wx1;
        const int y0 = (int)y0f, x0 = (int)x0f;
        const int y1 = y0 + 1, x1 = x0 + 1;
        const bool vy0 = (y0 >= 0) & (y0 < H_);
        const bool vy1 = (y1 >= 0) & (y1 < H_);
        const bool vx0 = (x0 >= 0) & (x0 < W_);
        const bool vx1 = (x1 >= 0) & (x1 < W_);
        const int cy0 = min(max(y0, 0), H_ - 1);
        const int cy1 = min(max(y1, 0), H_ - 1);
        const int cx0 = min(max(x0, 0), W_ - 1);
        const int cx1 = min(max(x1, 0), W_ - 1);
        const float m00 = (vy0 && vx0) ? wy0 * wx0 : 0.f;
        const float m01 = (vy0 && vx1) ? wy0 * wx1 : 0.f;
        const float m10 = (vy1 && vx0) ? wy1 * wx0 : 0.f;
        const float m11 = (vy1 && vx1) ? wy1 * wx1 : 0.f;
        const int i00 = cy0 * W_ + cx0, i01 = cy0 * W_ + cx1;
        const int i10 = cy1 * W_ + cx0, i11 = cy1 * W_ + cx1;

        const ulonglong2* wk2 = reinterpret_cast<const ulonglong2*>(wk_s);
        for (int c = 0; c < 64; ++c) {
            const float* xc = xb + c * HW_;
            const float v = m00 * __ldg(xc + i00) + m01 * __ldg(xc + i01)
                          + m10 * __ldg(xc + i10) + m11 * __ldg(xc + i11);
            const unsigned long long vv = pk2(v, v);
#pragma unroll
            for (int q = 0; q < 16; ++q) {
                ulonglong2 wv = wk2[c * 16 + q];   // 4 floats as 2 packed f32x2
                fma2(acc2[2 * q + 0], vv, wv.x);
                fma2(acc2[2 * q + 1], vv, wv.y);
            }
        }
    }

    const float mm = g_modmean[(size_t)b * HW_ + hw];
#pragma unroll
    for (int q = 0; q < 32; ++q) {
        float a0, a1;
        upk2(acc2[q], a0, a1);
        const int o = 2 * q;
        out[((size_t)b * 64 + o) * HW_ + hw]     = fmaf(a0, mm, __ldg(&bias[o]));
        out[((size_t)b * 64 + o + 1) * HW_ + hw] = fmaf(a1, mm, __ldg(&bias[o + 1]));
    }
}

// ---------------------------------------------------------------------------
extern "C" void kernel_launch(void* const* d_in, const int* in_sizes, int n_in,
                              void* d_out, int out_size)
{
    const float* x      = (const float*)d_in[0];
    const float* weight = (const float*)d_in[1];
    const float* bias   = (const float*)d_in[2];
    const float* ow     = (const float*)d_in[3];
    const float* ob     = (const float*)d_in[4];
    const float* mw     = (const float*)d_in[5];
    const float* mb     = (const float*)d_in[6];
    float* out = (float*)d_out;

    const size_t sm1_bytes = (size_t)(64 * 324 + 64 * 9 * 28) * sizeof(float); // 147456
    cudaFuncSetAttribute(k_offmod, cudaFuncAttributeMaxDynamicSharedMemorySize,
                         (int)sm1_bytes);

    dim3 grd(W_ / 16, H_ / 16, B_);
    k_offmod<<<grd, 256, sm1_bytes>>>(x, ow, ob, mw, mb);
    k_main<<<grd, 256>>>(x, weight, bias, out);
}